// round 1
// baseline (speedup 1.0000x reference)
#include <cuda_runtime.h>
#include <cstdint>

#define N_PROD 100000
#define N_CUST 50000
#define HID    128
#define DOUT   64
#define E_PP   800000
#define E_PC   800000
#define E_LB   400000

// ---------------------------------------------------------------------------
// Scratch (device globals: allocation-free per harness rules)
// ---------------------------------------------------------------------------
__device__ float g_bufP0[(size_t)N_PROD * HID];
__device__ float g_bufP1[(size_t)N_PROD * HID];
__device__ float g_bufP2[(size_t)N_PROD * HID];
__device__ float g_bufP3[(size_t)N_PROD * HID];
__device__ float g_bufC0[(size_t)N_CUST * HID];
__device__ float g_bufC1[(size_t)N_CUST * HID];
__device__ float g_bufC2[(size_t)N_CUST * HID];
__device__ float g_zprod[(size_t)N_PROD * DOUT];
__device__ float g_zcust[(size_t)N_CUST * DOUT];

__device__ int g_cnt[N_PROD];        // reused for P and C histograms
__device__ int g_offP[N_PROD];
__device__ int g_curP[N_PROD];
__device__ int g_csrP[E_PP];
__device__ int g_offC[N_CUST];
__device__ int g_curC[N_CUST];
__device__ int g_csrC[E_PC];
__device__ int g_bsums[256];

// ---------------------------------------------------------------------------
// CSR build: zero -> count -> scan (3 kernels) -> fill
// ---------------------------------------------------------------------------
__global__ void k_zero_int(int* p, int n) {
    int i = blockIdx.x * blockDim.x + threadIdx.x;
    if (i < n) p[i] = 0;
}

__global__ void k_count(const int* __restrict__ dst, int E, int* __restrict__ cnt) {
    int e = blockIdx.x * blockDim.x + threadIdx.x;
    if (e < E) atomicAdd(&cnt[dst[e]], 1);
}

__global__ void k_scan1(const int* __restrict__ cnt, int n, int* __restrict__ excl,
                        int* __restrict__ bsums) {
    __shared__ int s[1024];
    int gid = blockIdx.x * 1024 + threadIdx.x;
    int v = (gid < n) ? cnt[gid] : 0;
    s[threadIdx.x] = v;
    __syncthreads();
#pragma unroll
    for (int d = 1; d < 1024; d <<= 1) {
        int t = (threadIdx.x >= d) ? s[threadIdx.x - d] : 0;
        __syncthreads();
        s[threadIdx.x] += t;
        __syncthreads();
    }
    if (gid < n) excl[gid] = s[threadIdx.x] - v;
    if (threadIdx.x == 1023) bsums[blockIdx.x] = s[1023];
}

__global__ void k_scan2(int* bsums, int nb) {
    __shared__ int s[1024];
    int v = (threadIdx.x < nb) ? bsums[threadIdx.x] : 0;
    s[threadIdx.x] = v;
    __syncthreads();
#pragma unroll
    for (int d = 1; d < 1024; d <<= 1) {
        int t = (threadIdx.x >= d) ? s[threadIdx.x - d] : 0;
        __syncthreads();
        s[threadIdx.x] += t;
        __syncthreads();
    }
    if (threadIdx.x < nb) bsums[threadIdx.x] = s[threadIdx.x] - v;
}

__global__ void k_scan3(int* __restrict__ off, int* __restrict__ cur,
                        const int* __restrict__ bsums, int n) {
    int gid = blockIdx.x * 1024 + threadIdx.x;
    if (gid < n) {
        int v = off[gid] + bsums[blockIdx.x];
        off[gid] = v;
        cur[gid] = v;
    }
}

__global__ void k_fill(const int* __restrict__ src, const int* __restrict__ dst, int E,
                       int* __restrict__ cur, int* __restrict__ csr) {
    int e = blockIdx.x * blockDim.x + threadIdx.x;
    if (e < E) {
        int d = dst[e];
        int p = atomicAdd(&cur[d], 1);
        csr[p] = src[e];
    }
}

// ---------------------------------------------------------------------------
// Gather-side mean aggregation: one warp per destination node
// ---------------------------------------------------------------------------
__global__ void agg_mean(const float* __restrict__ x, const int* __restrict__ off,
                         const int* __restrict__ csr, float* __restrict__ outbuf,
                         int n, int E) {
    int w = (blockIdx.x * blockDim.x + threadIdx.x) >> 5;
    int lane = threadIdx.x & 31;
    if (w >= n) return;
    int beg = off[w];
    int end = (w + 1 < n) ? off[w + 1] : E;
    float4 acc = make_float4(0.f, 0.f, 0.f, 0.f);
    int j = beg;
    for (; j + 1 < end; j += 2) {
        int s0 = csr[j], s1 = csr[j + 1];
        float4 v0 = __ldg(reinterpret_cast<const float4*>(x + (size_t)s0 * HID + lane * 4));
        float4 v1 = __ldg(reinterpret_cast<const float4*>(x + (size_t)s1 * HID + lane * 4));
        acc.x += v0.x + v1.x; acc.y += v0.y + v1.y;
        acc.z += v0.z + v1.z; acc.w += v0.w + v1.w;
    }
    if (j < end) {
        int s0 = csr[j];
        float4 v0 = __ldg(reinterpret_cast<const float4*>(x + (size_t)s0 * HID + lane * 4));
        acc.x += v0.x; acc.y += v0.y; acc.z += v0.z; acc.w += v0.w;
    }
    float sc = (end > beg) ? 1.0f / (float)(end - beg) : 0.f;
    acc.x *= sc; acc.y *= sc; acc.z *= sc; acc.w *= sc;
    *reinterpret_cast<float4*>(outbuf + (size_t)w * HID + lane * 4) = acc;
}

// ---------------------------------------------------------------------------
// Fused dual/single GEMM:
//   DUAL:   out = act(A @ Wl^T + b + X @ Wr^T)    (NO=128)
//   single: out = A @ Wl^T + b                    (NO=64)
// Weight-stationary in SMEM (transposed [k][o], +4 pad), 16 warps x 4 rows.
// ---------------------------------------------------------------------------
template <int NO, bool DUAL, bool RELU>
__launch_bounds__(512, 1)
__global__ void sage_gemm(const float* __restrict__ A, const float* __restrict__ X,
                          const float* __restrict__ Wl, const float* __restrict__ Wr,
                          const float* __restrict__ bias, float* __restrict__ out, int n) {
    constexpr int NOP = NO + 4;
    constexpr int NC = NO / 32;
    constexpr int WARPS = 16;
    constexpr int R = 4;
    constexpr int MULT = DUAL ? 2 : 1;

    extern __shared__ float smem[];
    float* Wls = smem;
    float* Wrs = smem + 128 * NOP;
    float* stage = smem + MULT * 128 * NOP;

    int tid = threadIdx.x;
    for (int i = tid; i < NO * 128; i += 512) {
        int o = i >> 7, k = i & 127;
        Wls[k * NOP + o] = Wl[i];
        if (DUAL) Wrs[k * NOP + o] = Wr[i];
    }
    __syncthreads();

    const int w = tid >> 5, lane = tid & 31;
    float* As = stage + w * (R * 128 * MULT);
    float* Xs = As + R * 128;  // only used when DUAL

    float bofs[NC];
#pragma unroll
    for (int j = 0; j < NC; j++) bofs[j] = __ldg(bias + lane * NC + j);

    for (int base = (blockIdx.x * WARPS + w) * R; base < n; base += gridDim.x * WARPS * R) {
#pragma unroll
        for (int r = 0; r < R; r++) {
            int row = base + r;
            float4 av = make_float4(0.f, 0.f, 0.f, 0.f);
            float4 xv = av;
            if (row < n) {
                av = *reinterpret_cast<const float4*>(A + (size_t)row * 128 + lane * 4);
                if (DUAL) xv = *reinterpret_cast<const float4*>(X + (size_t)row * 128 + lane * 4);
            }
            *reinterpret_cast<float4*>(As + r * 128 + lane * 4) = av;
            if (DUAL) *reinterpret_cast<float4*>(Xs + r * 128 + lane * 4) = xv;
        }
        __syncwarp();

        float acc[R][NC];
#pragma unroll
        for (int r = 0; r < R; r++)
#pragma unroll
            for (int j = 0; j < NC; j++) acc[r][j] = bofs[j];

#pragma unroll 8
        for (int k = 0; k < 128; k++) {
            float wl[NC], wr[NC];
            if (NC == 4) {
                float4 t = *reinterpret_cast<const float4*>(Wls + k * NOP + lane * 4);
                wl[0] = t.x; wl[1] = t.y; wl[2] = t.z; wl[3] = t.w;
                if (DUAL) {
                    float4 u = *reinterpret_cast<const float4*>(Wrs + k * NOP + lane * 4);
                    wr[0] = u.x; wr[1] = u.y; wr[2] = u.z; wr[3] = u.w;
                }
            } else {
                float2 t = *reinterpret_cast<const float2*>(Wls + k * NOP + lane * 2);
                wl[0] = t.x; wl[1] = t.y;
                if (DUAL) {
                    float2 u = *reinterpret_cast<const float2*>(Wrs + k * NOP + lane * 2);
                    wr[0] = u.x; wr[1] = u.y;
                }
            }
#pragma unroll
            for (int r = 0; r < R; r++) {
                float a = As[r * 128 + k];
#pragma unroll
                for (int j = 0; j < NC; j++) acc[r][j] = fmaf(a, wl[j], acc[r][j]);
                if (DUAL) {
                    float xval = Xs[r * 128 + k];
#pragma unroll
                    for (int j = 0; j < NC; j++) acc[r][j] = fmaf(xval, wr[j], acc[r][j]);
                }
            }
        }

#pragma unroll
        for (int r = 0; r < R; r++) {
            int row = base + r;
            if (row < n) {
#pragma unroll
                for (int j = 0; j < NC; j++) {
                    float v = acc[r][j];
                    if (RELU) v = fmaxf(v, 0.f);
                    out[(size_t)row * NO + lane * NC + j] = v;
                }
            }
        }
        __syncwarp();
    }
}

// ---------------------------------------------------------------------------
// Decoder: out[e] = b2 + w2 . relu(de_W1 @ [zc[row[e]], zp[col[e]]] + b1)
// ---------------------------------------------------------------------------
__launch_bounds__(512, 1)
__global__ void decoder_kernel(const float* __restrict__ zc, const float* __restrict__ zp,
                               const int* __restrict__ row, const int* __restrict__ col,
                               const float* __restrict__ W1, const float* __restrict__ b1,
                               const float* __restrict__ w2, const float* __restrict__ b2,
                               float* __restrict__ out, int nE) {
    constexpr int NOP = 68;
    extern __shared__ float smem[];
    float* Ws = smem;                  // 128 * 68
    float* stage = smem + 128 * NOP;   // 16 warps * 4 edges * 128

    int tid = threadIdx.x;
    for (int i = tid; i < 64 * 128; i += 512) {
        int o = i >> 7, k = i & 127;
        Ws[k * NOP + o] = W1[i];
    }
    __syncthreads();

    const int w = tid >> 5, lane = tid & 31;
    float* Zs = stage + w * (4 * 128);

    float bb0 = __ldg(b1 + lane * 2), bb1 = __ldg(b1 + lane * 2 + 1);
    float w20 = __ldg(w2 + lane * 2), w21 = __ldg(w2 + lane * 2 + 1);
    float b2v = __ldg(b2);

    for (int base = (blockIdx.x * 16 + w) * 4; base < nE; base += gridDim.x * 64) {
#pragma unroll
        for (int r = 0; r < 4; r++) {
            int e = base + r;
            float4 v = make_float4(0.f, 0.f, 0.f, 0.f);
            if (e < nE) {
                if (lane < 16) {
                    int ri = __ldg(row + e);
                    v = *reinterpret_cast<const float4*>(zc + (size_t)ri * DOUT + lane * 4);
                } else {
                    int ci = __ldg(col + e);
                    v = *reinterpret_cast<const float4*>(zp + (size_t)ci * DOUT + (lane - 16) * 4);
                }
            }
            *reinterpret_cast<float4*>(Zs + r * 128 + lane * 4) = v;
        }
        __syncwarp();

        float acc[4][2];
#pragma unroll
        for (int r = 0; r < 4; r++) { acc[r][0] = bb0; acc[r][1] = bb1; }

#pragma unroll 8
        for (int k = 0; k < 128; k++) {
            float2 t = *reinterpret_cast<const float2*>(Ws + k * NOP + lane * 2);
#pragma unroll
            for (int r = 0; r < 4; r++) {
                float z = Zs[r * 128 + k];
                acc[r][0] = fmaf(z, t.x, acc[r][0]);
                acc[r][1] = fmaf(z, t.y, acc[r][1]);
            }
        }

#pragma unroll
        for (int r = 0; r < 4; r++) {
            float h0 = fmaxf(acc[r][0], 0.f), h1 = fmaxf(acc[r][1], 0.f);
            float p = h0 * w20 + h1 * w21;
#pragma unroll
            for (int o = 16; o > 0; o >>= 1) p += __shfl_xor_sync(0xffffffff, p, o);
            if (lane == 0 && base + r < nE) out[base + r] = p + b2v;
        }
        __syncwarp();
    }
}

// ---------------------------------------------------------------------------
// Host orchestration
// ---------------------------------------------------------------------------
static void build_csr(const int* src, const int* dst, int E, int n,
                      int* cnt, int* off, int* cur, int* csr, int* bsums) {
    k_zero_int<<<(n + 255) / 256, 256>>>(cnt, n);
    k_count<<<(E + 255) / 256, 256>>>(dst, E, cnt);
    int nb = (n + 1023) / 1024;
    k_scan1<<<nb, 1024>>>(cnt, n, off, bsums);
    k_scan2<<<1, 1024>>>(bsums, nb);
    k_scan3<<<nb, 1024>>>(off, cur, bsums, n);
    k_fill<<<(E + 255) / 256, 256>>>(src, dst, E, cur, csr);
}

extern "C" void kernel_launch(void* const* d_in, const int* in_sizes, int n_in,
                              void* d_out, int out_size) {
    const float* x_prod = (const float*)d_in[0];
    const float* x_cust = (const float*)d_in[1];
    const int* pp = (const int*)d_in[2];
    const int* pc = (const int*)d_in[3];
    const int* eli = (const int*)d_in[4];

    // Detect weight/bias ordering: signature order has it_b1 (128 elems) at index 6.
    bool sig = (in_sizes[6] == HID);
    const float* it_W1l = (const float*)d_in[5];
    const float* it_W1r = (const float*)d_in[sig ? 7 : 6];
    const float* it_b1  = (const float*)d_in[sig ? 6 : 7];
    const float* it_W2l = (const float*)d_in[8];
    const float* it_W2r = (const float*)d_in[sig ? 10 : 9];
    const float* it_b2  = (const float*)d_in[sig ? 9 : 10];
    const float* it_Wlin = (const float*)d_in[11];
    const float* it_blin = (const float*)d_in[12];
    const float* us_W1l = (const float*)d_in[13];
    const float* us_W1r = (const float*)d_in[sig ? 15 : 14];
    const float* us_b1  = (const float*)d_in[sig ? 14 : 15];
    const float* us_W2l = (const float*)d_in[16];
    const float* us_W2r = (const float*)d_in[sig ? 18 : 17];
    const float* us_b2  = (const float*)d_in[sig ? 17 : 18];
    const float* us_W3l = (const float*)d_in[19];
    const float* us_W3r = (const float*)d_in[sig ? 21 : 20];
    const float* us_b3  = (const float*)d_in[sig ? 20 : 21];
    const float* us_Wlin = (const float*)d_in[22];
    const float* us_blin = (const float*)d_in[23];
    const float* de_W1 = (const float*)d_in[24];
    const float* de_b1 = (const float*)d_in[25];
    const float* de_W2 = (const float*)d_in[26];
    const float* de_b2 = (const float*)d_in[27];

    // Resolve scratch addresses
    float *bufP0, *bufP1, *bufP2, *bufP3, *bufC0, *bufC1, *bufC2, *zprod, *zcust;
    int *cnt, *offP, *curP, *csrP, *offC, *curC, *csrC, *bsums;
    cudaGetSymbolAddress((void**)&bufP0, g_bufP0);
    cudaGetSymbolAddress((void**)&bufP1, g_bufP1);
    cudaGetSymbolAddress((void**)&bufP2, g_bufP2);
    cudaGetSymbolAddress((void**)&bufP3, g_bufP3);
    cudaGetSymbolAddress((void**)&bufC0, g_bufC0);
    cudaGetSymbolAddress((void**)&bufC1, g_bufC1);
    cudaGetSymbolAddress((void**)&bufC2, g_bufC2);
    cudaGetSymbolAddress((void**)&zprod, g_zprod);
    cudaGetSymbolAddress((void**)&zcust, g_zcust);
    cudaGetSymbolAddress((void**)&cnt, g_cnt);
    cudaGetSymbolAddress((void**)&offP, g_offP);
    cudaGetSymbolAddress((void**)&curP, g_curP);
    cudaGetSymbolAddress((void**)&csrP, g_csrP);
    cudaGetSymbolAddress((void**)&offC, g_offC);
    cudaGetSymbolAddress((void**)&curC, g_curC);
    cudaGetSymbolAddress((void**)&csrC, g_csrC);
    cudaGetSymbolAddress((void**)&bsums, g_bsums);

    constexpr int SMEM_DUAL = (2 * 128 * 132 + 16 * 4 * 128 * 2) * 4;   // 200704
    constexpr int SMEM_SINGLE = (128 * 68 + 16 * 4 * 128) * 4;          // 67584
    constexpr int SMEM_DEC = (128 * 68 + 16 * 4 * 128) * 4;             // 67584
    cudaFuncSetAttribute(sage_gemm<128, true, true>,
                         cudaFuncAttributeMaxDynamicSharedMemorySize, SMEM_DUAL);
    cudaFuncSetAttribute(sage_gemm<64, false, false>,
                         cudaFuncAttributeMaxDynamicSharedMemorySize, SMEM_SINGLE);
    cudaFuncSetAttribute(decoder_kernel,
                         cudaFuncAttributeMaxDynamicSharedMemorySize, SMEM_DEC);

    // CSR for the two edge types
    build_csr(pp, pp + E_PP, E_PP, N_PROD, cnt, offP, curP, csrP, bsums);
    build_csr(pc, pc + E_PC, E_PC, N_CUST, cnt, offC, curC, csrC, bsums);

    const int aggP_grid = (N_PROD * 32 + 255) / 256;
    const int aggC_grid = (N_CUST * 32 + 255) / 256;

    // ItemGNN + shared first product aggregation
    agg_mean<<<aggP_grid, 256>>>(x_prod, offP, csrP, bufP0, N_PROD, E_PP);   // mean_pp(x_prod)
    sage_gemm<128, true, true><<<148, 512, SMEM_DUAL>>>(bufP0, x_prod, it_W1l, it_W1r, it_b1, bufP1, N_PROD);  // p1
    sage_gemm<128, true, true><<<148, 512, SMEM_DUAL>>>(bufP0, x_prod, us_W1l, us_W1r, us_b1, bufP2, N_PROD);  // px
    agg_mean<<<aggP_grid, 256>>>(bufP1, offP, csrP, bufP0, N_PROD, E_PP);    // mean_pp(p1)
    sage_gemm<128, true, true><<<148, 512, SMEM_DUAL>>>(bufP0, bufP1, it_W2l, it_W2r, it_b2, bufP3, N_PROD);   // p2
    sage_gemm<64, false, false><<<296, 512, SMEM_SINGLE>>>(bufP3, nullptr, it_Wlin, nullptr, it_blin, zprod, N_PROD);

    // UserGNN
    agg_mean<<<aggC_grid, 256>>>(x_prod, offC, csrC, bufC0, N_CUST, E_PC);   // mean_pc(x_prod)
    sage_gemm<128, true, true><<<148, 512, SMEM_DUAL>>>(bufC0, x_cust, us_W2l, us_W2r, us_b2, bufC1, N_CUST);  // cx
    agg_mean<<<aggC_grid, 256>>>(bufP2, offC, csrC, bufC0, N_CUST, E_PC);    // mean_pc(px)
    sage_gemm<128, true, true><<<148, 512, SMEM_DUAL>>>(bufC0, bufC1, us_W3l, us_W3r, us_b3, bufC2, N_CUST);   // cx2
    sage_gemm<64, false, false><<<296, 512, SMEM_SINGLE>>>(bufC2, nullptr, us_Wlin, nullptr, us_blin, zcust, N_CUST);

    // Edge decoder
    decoder_kernel<<<296, 512, SMEM_DEC>>>(zcust, zprod, eli, eli + E_LB,
                                           de_W1, de_b1, de_W2, de_b2,
                                           (float*)d_out, E_LB);
}

// round 2
// speedup vs baseline: 1.0888x; 1.0888x over previous
#include <cuda_runtime.h>
#include <cstdint>

#define N_PROD 100000
#define N_CUST 50000
#define HID    128
#define DOUT   64
#define E_PP   800000
#define E_PC   800000
#define E_LB   400000

typedef unsigned long long u64;

// ---------------------------------------------------------------------------
// f32x2 packed-FMA helpers (Blackwell FFMA2 — only reachable via PTX)
// ---------------------------------------------------------------------------
__device__ __forceinline__ u64 pack2(float lo, float hi) {
    u64 r; asm("mov.b64 %0,{%1,%2};" : "=l"(r) : "f"(lo), "f"(hi)); return r;
}
__device__ __forceinline__ u64 dup2(float a) {
    u64 r; asm("mov.b64 %0,{%1,%1};" : "=l"(r) : "f"(a)); return r;
}
__device__ __forceinline__ void fma2(u64& d, u64 a, u64 b) {
    asm("fma.rn.f32x2 %0,%1,%2,%0;" : "+l"(d) : "l"(a), "l"(b));
}
__device__ __forceinline__ void unpack2(u64 v, float& lo, float& hi) {
    asm("mov.b64 {%0,%1},%2;" : "=f"(lo), "=f"(hi) : "l"(v));
}

// ---------------------------------------------------------------------------
// Scratch (device globals: allocation-free per harness rules)
// ---------------------------------------------------------------------------
__device__ float g_bufP0[(size_t)N_PROD * HID];
__device__ float g_bufP1[(size_t)N_PROD * HID];
__device__ float g_bufP2[(size_t)N_PROD * HID];
__device__ float g_bufP3[(size_t)N_PROD * HID];
__device__ float g_bufC0[(size_t)N_CUST * HID];
__device__ float g_bufC1[(size_t)N_CUST * HID];
__device__ float g_bufC2[(size_t)N_CUST * HID];
__device__ float g_zprod[(size_t)N_PROD * DOUT];
__device__ float g_zcust[(size_t)N_CUST * DOUT];

__device__ int g_cnt[N_PROD];
__device__ int g_offP[N_PROD];
__device__ int g_curP[N_PROD];
__device__ int g_csrP[E_PP];
__device__ int g_offC[N_CUST];
__device__ int g_curC[N_CUST];
__device__ int g_csrC[E_PC];
__device__ int g_bsums[256];

// ---------------------------------------------------------------------------
// CSR build: zero -> count -> scan (3 kernels) -> fill
// ---------------------------------------------------------------------------
__global__ void k_zero_int(int* p, int n) {
    int i = blockIdx.x * blockDim.x + threadIdx.x;
    if (i < n) p[i] = 0;
}

__global__ void k_count(const int* __restrict__ dst, int E, int* __restrict__ cnt) {
    int e = blockIdx.x * blockDim.x + threadIdx.x;
    if (e < E) atomicAdd(&cnt[dst[e]], 1);
}

__global__ void k_scan1(const int* __restrict__ cnt, int n, int* __restrict__ excl,
                        int* __restrict__ bsums) {
    __shared__ int s[1024];
    int gid = blockIdx.x * 1024 + threadIdx.x;
    int v = (gid < n) ? cnt[gid] : 0;
    s[threadIdx.x] = v;
    __syncthreads();
#pragma unroll
    for (int d = 1; d < 1024; d <<= 1) {
        int t = (threadIdx.x >= d) ? s[threadIdx.x - d] : 0;
        __syncthreads();
        s[threadIdx.x] += t;
        __syncthreads();
    }
    if (gid < n) excl[gid] = s[threadIdx.x] - v;
    if (threadIdx.x == 1023) bsums[blockIdx.x] = s[1023];
}

__global__ void k_scan2(int* bsums, int nb) {
    __shared__ int s[1024];
    int v = (threadIdx.x < nb) ? bsums[threadIdx.x] : 0;
    s[threadIdx.x] = v;
    __syncthreads();
#pragma unroll
    for (int d = 1; d < 1024; d <<= 1) {
        int t = (threadIdx.x >= d) ? s[threadIdx.x - d] : 0;
        __syncthreads();
        s[threadIdx.x] += t;
        __syncthreads();
    }
    if (threadIdx.x < nb) bsums[threadIdx.x] = s[threadIdx.x] - v;
}

__global__ void k_scan3(int* __restrict__ off, int* __restrict__ cur,
                        const int* __restrict__ bsums, int n) {
    int gid = blockIdx.x * 1024 + threadIdx.x;
    if (gid < n) {
        int v = off[gid] + bsums[blockIdx.x];
        off[gid] = v;
        cur[gid] = v;
    }
}

__global__ void k_fill(const int* __restrict__ src, const int* __restrict__ dst, int E,
                       int* __restrict__ cur, int* __restrict__ csr) {
    int e = blockIdx.x * blockDim.x + threadIdx.x;
    if (e < E) {
        int d = dst[e];
        int p = atomicAdd(&cur[d], 1);
        csr[p] = src[e];
    }
}

// ---------------------------------------------------------------------------
// Gather-side mean aggregation: one warp per destination node
// ---------------------------------------------------------------------------
__global__ void agg_mean(const float* __restrict__ x, const int* __restrict__ off,
                         const int* __restrict__ csr, float* __restrict__ outbuf,
                         int n, int E) {
    int w = (blockIdx.x * blockDim.x + threadIdx.x) >> 5;
    int lane = threadIdx.x & 31;
    if (w >= n) return;
    int beg = off[w];
    int end = (w + 1 < n) ? off[w + 1] : E;
    float4 acc = make_float4(0.f, 0.f, 0.f, 0.f);
    int j = beg;
    for (; j + 1 < end; j += 2) {
        int s0 = csr[j], s1 = csr[j + 1];
        float4 v0 = __ldg(reinterpret_cast<const float4*>(x + (size_t)s0 * HID + lane * 4));
        float4 v1 = __ldg(reinterpret_cast<const float4*>(x + (size_t)s1 * HID + lane * 4));
        acc.x += v0.x + v1.x; acc.y += v0.y + v1.y;
        acc.z += v0.z + v1.z; acc.w += v0.w + v1.w;
    }
    if (j < end) {
        int s0 = csr[j];
        float4 v0 = __ldg(reinterpret_cast<const float4*>(x + (size_t)s0 * HID + lane * 4));
        acc.x += v0.x; acc.y += v0.y; acc.z += v0.z; acc.w += v0.w;
    }
    float sc = (end > beg) ? 1.0f / (float)(end - beg) : 0.f;
    acc.x *= sc; acc.y *= sc; acc.z *= sc; acc.w *= sc;
    *reinterpret_cast<float4*>(outbuf + (size_t)w * HID + lane * 4) = acc;
}

// ---------------------------------------------------------------------------
// Fused dual/single GEMM with packed f32x2 FMAs:
//   DUAL:   out = act(A @ Wl^T + b + X @ Wr^T)    (NO=128)
//   single: out = A @ Wl^T + b                    (NO=64)
// Weight-stationary in SMEM (transposed [k][o], +4 pad).
// ---------------------------------------------------------------------------
template <int NO, bool DUAL, bool RELU>
__launch_bounds__(512, 1)
__global__ void sage_gemm(const float* __restrict__ A, const float* __restrict__ X,
                          const float* __restrict__ Wl, const float* __restrict__ Wr,
                          const float* __restrict__ bias, float* __restrict__ out, int n) {
    constexpr int NOP = NO + 4;
    constexpr int NC = NO / 32;   // outputs per lane (4 or 2)
    constexpr int NP = NC / 2;    // f32x2 accumulators per lane per row
    constexpr int WARPS = 16;
    constexpr int R = DUAL ? 4 : 8;
    constexpr int MULT = DUAL ? 2 : 1;

    extern __shared__ float smem[];
    float* Wls = smem;
    float* Wrs = smem + 128 * NOP;
    float* stage = smem + MULT * 128 * NOP;

    int tid = threadIdx.x;
    for (int i = tid; i < NO * 128; i += 512) {
        int o = i >> 7, k = i & 127;
        Wls[k * NOP + o] = Wl[i];
        if (DUAL) Wrs[k * NOP + o] = Wr[i];
    }
    __syncthreads();

    const int w = tid >> 5, lane = tid & 31;
    float* As = stage + w * (R * 128 * MULT);
    float* Xs = As + R * 128;  // only used when DUAL

    u64 bofs[NP];
    if (NP == 2) {
        float4 b4 = __ldg(reinterpret_cast<const float4*>(bias + lane * 4));
        bofs[0] = pack2(b4.x, b4.y); bofs[1] = pack2(b4.z, b4.w);
    } else {
        float2 b2 = __ldg(reinterpret_cast<const float2*>(bias + lane * 2));
        bofs[0] = pack2(b2.x, b2.y);
    }

    for (int base = (blockIdx.x * WARPS + w) * R; base < n; base += gridDim.x * WARPS * R) {
#pragma unroll
        for (int r = 0; r < R; r++) {
            int row = base + r;
            float4 av = make_float4(0.f, 0.f, 0.f, 0.f);
            float4 xv = av;
            if (row < n) {
                av = *reinterpret_cast<const float4*>(A + (size_t)row * 128 + lane * 4);
                if (DUAL) xv = *reinterpret_cast<const float4*>(X + (size_t)row * 128 + lane * 4);
            }
            *reinterpret_cast<float4*>(As + r * 128 + lane * 4) = av;
            if (DUAL) *reinterpret_cast<float4*>(Xs + r * 128 + lane * 4) = xv;
        }
        __syncwarp();

        u64 acc[R][NP];
#pragma unroll
        for (int r = 0; r < R; r++)
#pragma unroll
            for (int j = 0; j < NP; j++) acc[r][j] = bofs[j];

        for (int k0 = 0; k0 < 128; k0 += 4) {
            float4 a4[R], x4[R];
#pragma unroll
            for (int r = 0; r < R; r++) {
                a4[r] = *reinterpret_cast<const float4*>(As + r * 128 + k0);
                if (DUAL) x4[r] = *reinterpret_cast<const float4*>(Xs + r * 128 + k0);
            }
#pragma unroll
            for (int kk = 0; kk < 4; kk++) {
                int k = k0 + kk;
                u64 wl[NP], wr[NP];
                if (NP == 2) {
                    ulonglong2 t = *reinterpret_cast<const ulonglong2*>(Wls + k * NOP + lane * 4);
                    wl[0] = t.x; wl[1] = t.y;
                    if (DUAL) {
                        ulonglong2 u_ = *reinterpret_cast<const ulonglong2*>(Wrs + k * NOP + lane * 4);
                        wr[0] = u_.x; wr[1] = u_.y;
                    }
                } else {
                    wl[0] = *reinterpret_cast<const u64*>(Wls + k * NOP + lane * 2);
                    if (DUAL) wr[0] = *reinterpret_cast<const u64*>(Wrs + k * NOP + lane * 2);
                }
#pragma unroll
                for (int r = 0; r < R; r++) {
                    float a = (kk == 0) ? a4[r].x : (kk == 1) ? a4[r].y : (kk == 2) ? a4[r].z : a4[r].w;
                    u64 ad = dup2(a);
#pragma unroll
                    for (int j = 0; j < NP; j++) fma2(acc[r][j], ad, wl[j]);
                    if (DUAL) {
                        float xx = (kk == 0) ? x4[r].x : (kk == 1) ? x4[r].y : (kk == 2) ? x4[r].z : x4[r].w;
                        u64 xd = dup2(xx);
#pragma unroll
                        for (int j = 0; j < NP; j++) fma2(acc[r][j], xd, wr[j]);
                    }
                }
            }
        }

#pragma unroll
        for (int r = 0; r < R; r++) {
            int row = base + r;
            if (row < n) {
                if (NP == 2) {
                    float o0, o1, o2, o3;
                    unpack2(acc[r][0], o0, o1);
                    unpack2(acc[r][1], o2, o3);
                    if (RELU) {
                        o0 = fmaxf(o0, 0.f); o1 = fmaxf(o1, 0.f);
                        o2 = fmaxf(o2, 0.f); o3 = fmaxf(o3, 0.f);
                    }
                    *reinterpret_cast<float4*>(out + (size_t)row * NO + lane * 4) =
                        make_float4(o0, o1, o2, o3);
                } else {
                    float o0, o1;
                    unpack2(acc[r][0], o0, o1);
                    if (RELU) { o0 = fmaxf(o0, 0.f); o1 = fmaxf(o1, 0.f); }
                    *reinterpret_cast<float2*>(out + (size_t)row * NO + lane * 2) =
                        make_float2(o0, o1);
                }
            }
        }
        __syncwarp();
    }
}

// ---------------------------------------------------------------------------
// Decoder: out[e] = b2 + w2 . relu(de_W1 @ [zc[row[e]], zp[col[e]]] + b1)
// R=8 edges per warp, packed f32x2 FMAs.
// ---------------------------------------------------------------------------
__launch_bounds__(512, 1)
__global__ void decoder_kernel(const float* __restrict__ zc, const float* __restrict__ zp,
                               const int* __restrict__ row, const int* __restrict__ col,
                               const float* __restrict__ W1, const float* __restrict__ b1,
                               const float* __restrict__ w2, const float* __restrict__ b2,
                               float* __restrict__ out, int nE) {
    constexpr int NOP = 68;
    constexpr int R = 8;
    extern __shared__ float smem[];
    float* Ws = smem;                  // 128 * 68
    float* stage = smem + 128 * NOP;   // 16 warps * 8 edges * 128

    int tid = threadIdx.x;
    for (int i = tid; i < 64 * 128; i += 512) {
        int o = i >> 7, k = i & 127;
        Ws[k * NOP + o] = W1[i];
    }
    __syncthreads();

    const int w = tid >> 5, lane = tid & 31;
    float* Zs = stage + w * (R * 128);

    float2 b1v = __ldg(reinterpret_cast<const float2*>(b1 + lane * 2));
    u64 bofs = pack2(b1v.x, b1v.y);
    float w20 = __ldg(w2 + lane * 2), w21 = __ldg(w2 + lane * 2 + 1);
    float b2v = __ldg(b2);

    for (int base = (blockIdx.x * 16 + w) * R; base < nE; base += gridDim.x * 16 * R) {
#pragma unroll
        for (int r = 0; r < R; r++) {
            int e = base + r;
            float4 v = make_float4(0.f, 0.f, 0.f, 0.f);
            if (e < nE) {
                if (lane < 16) {
                    int ri = __ldg(row + e);
                    v = *reinterpret_cast<const float4*>(zc + (size_t)ri * DOUT + lane * 4);
                } else {
                    int ci = __ldg(col + e);
                    v = *reinterpret_cast<const float4*>(zp + (size_t)ci * DOUT + (lane - 16) * 4);
                }
            }
            *reinterpret_cast<float4*>(Zs + r * 128 + lane * 4) = v;
        }
        __syncwarp();

        u64 acc[R];
#pragma unroll
        for (int r = 0; r < R; r++) acc[r] = bofs;

        for (int k0 = 0; k0 < 128; k0 += 4) {
            float4 z4[R];
#pragma unroll
            for (int r = 0; r < R; r++)
                z4[r] = *reinterpret_cast<const float4*>(Zs + r * 128 + k0);
#pragma unroll
            for (int kk = 0; kk < 4; kk++) {
                u64 wv = *reinterpret_cast<const u64*>(Ws + (k0 + kk) * NOP + lane * 2);
#pragma unroll
                for (int r = 0; r < R; r++) {
                    float z = (kk == 0) ? z4[r].x : (kk == 1) ? z4[r].y : (kk == 2) ? z4[r].z : z4[r].w;
                    u64 zd = dup2(z);
                    fma2(acc[r], zd, wv);
                }
            }
        }

#pragma unroll
        for (int r = 0; r < R; r++) {
            float h0, h1;
            unpack2(acc[r], h0, h1);
            h0 = fmaxf(h0, 0.f); h1 = fmaxf(h1, 0.f);
            float p = h0 * w20 + h1 * w21;
#pragma unroll
            for (int o = 16; o > 0; o >>= 1) p += __shfl_xor_sync(0xffffffff, p, o);
            if (lane == 0 && base + r < nE) out[base + r] = p + b2v;
        }
        __syncwarp();
    }
}

// ---------------------------------------------------------------------------
// Host orchestration
// ---------------------------------------------------------------------------
static void build_csr(const int* src, const int* dst, int E, int n,
                      int* cnt, int* off, int* cur, int* csr, int* bsums) {
    k_zero_int<<<(n + 255) / 256, 256>>>(cnt, n);
    k_count<<<(E + 255) / 256, 256>>>(dst, E, cnt);
    int nb = (n + 1023) / 1024;
    k_scan1<<<nb, 1024>>>(cnt, n, off, bsums);
    k_scan2<<<1, 1024>>>(bsums, nb);
    k_scan3<<<nb, 1024>>>(off, cur, bsums, n);
    k_fill<<<(E + 255) / 256, 256>>>(src, dst, E, cur, csr);
}

extern "C" void kernel_launch(void* const* d_in, const int* in_sizes, int n_in,
                              void* d_out, int out_size) {
    const float* x_prod = (const float*)d_in[0];
    const float* x_cust = (const float*)d_in[1];
    const int* pp = (const int*)d_in[2];
    const int* pc = (const int*)d_in[3];
    const int* eli = (const int*)d_in[4];

    bool sig = (in_sizes[6] == HID);
    const float* it_W1l = (const float*)d_in[5];
    const float* it_W1r = (const float*)d_in[sig ? 7 : 6];
    const float* it_b1  = (const float*)d_in[sig ? 6 : 7];
    const float* it_W2l = (const float*)d_in[8];
    const float* it_W2r = (const float*)d_in[sig ? 10 : 9];
    const float* it_b2  = (const float*)d_in[sig ? 9 : 10];
    const float* it_Wlin = (const float*)d_in[11];
    const float* it_blin = (const float*)d_in[12];
    const float* us_W1l = (const float*)d_in[13];
    const float* us_W1r = (const float*)d_in[sig ? 15 : 14];
    const float* us_b1  = (const float*)d_in[sig ? 14 : 15];
    const float* us_W2l = (const float*)d_in[16];
    const float* us_W2r = (const float*)d_in[sig ? 18 : 17];
    const float* us_b2  = (const float*)d_in[sig ? 17 : 18];
    const float* us_W3l = (const float*)d_in[19];
    const float* us_W3r = (const float*)d_in[sig ? 21 : 20];
    const float* us_b3  = (const float*)d_in[sig ? 20 : 21];
    const float* us_Wlin = (const float*)d_in[22];
    const float* us_blin = (const float*)d_in[23];
    const float* de_W1 = (const float*)d_in[24];
    const float* de_b1 = (const float*)d_in[25];
    const float* de_W2 = (const float*)d_in[26];
    const float* de_b2 = (const float*)d_in[27];

    float *bufP0, *bufP1, *bufP2, *bufP3, *bufC0, *bufC1, *bufC2, *zprod, *zcust;
    int *cnt, *offP, *curP, *csrP, *offC, *curC, *csrC, *bsums;
    cudaGetSymbolAddress((void**)&bufP0, g_bufP0);
    cudaGetSymbolAddress((void**)&bufP1, g_bufP1);
    cudaGetSymbolAddress((void**)&bufP2, g_bufP2);
    cudaGetSymbolAddress((void**)&bufP3, g_bufP3);
    cudaGetSymbolAddress((void**)&bufC0, g_bufC0);
    cudaGetSymbolAddress((void**)&bufC1, g_bufC1);
    cudaGetSymbolAddress((void**)&bufC2, g_bufC2);
    cudaGetSymbolAddress((void**)&zprod, g_zprod);
    cudaGetSymbolAddress((void**)&zcust, g_zcust);
    cudaGetSymbolAddress((void**)&cnt, g_cnt);
    cudaGetSymbolAddress((void**)&offP, g_offP);
    cudaGetSymbolAddress((void**)&curP, g_curP);
    cudaGetSymbolAddress((void**)&csrP, g_csrP);
    cudaGetSymbolAddress((void**)&offC, g_offC);
    cudaGetSymbolAddress((void**)&curC, g_curC);
    cudaGetSymbolAddress((void**)&csrC, g_csrC);
    cudaGetSymbolAddress((void**)&bsums, g_bsums);

    constexpr int SMEM_DUAL   = (2 * 128 * 132 + 16 * 4 * 128 * 2) * 4;  // 200704
    constexpr int SMEM_SINGLE = (128 * 68 + 16 * 8 * 128) * 4;           // 100352
    constexpr int SMEM_DEC    = (128 * 68 + 16 * 8 * 128) * 4;           // 100352
    cudaFuncSetAttribute(sage_gemm<128, true, true>,
                         cudaFuncAttributeMaxDynamicSharedMemorySize, SMEM_DUAL);
    cudaFuncSetAttribute(sage_gemm<64, false, false>,
                         cudaFuncAttributeMaxDynamicSharedMemorySize, SMEM_SINGLE);
    cudaFuncSetAttribute(decoder_kernel,
                         cudaFuncAttributeMaxDynamicSharedMemorySize, SMEM_DEC);

    build_csr(pp, pp + E_PP, E_PP, N_PROD, cnt, offP, curP, csrP, bsums);
    build_csr(pc, pc + E_PC, E_PC, N_CUST, cnt, offC, curC, csrC, bsums);

    const int aggP_grid = (N_PROD * 32 + 255) / 256;
    const int aggC_grid = (N_CUST * 32 + 255) / 256;

    // ItemGNN + shared first product aggregation
    agg_mean<<<aggP_grid, 256>>>(x_prod, offP, csrP, bufP0, N_PROD, E_PP);
    sage_gemm<128, true, true><<<148, 512, SMEM_DUAL>>>(bufP0, x_prod, it_W1l, it_W1r, it_b1, bufP1, N_PROD);
    sage_gemm<128, true, true><<<148, 512, SMEM_DUAL>>>(bufP0, x_prod, us_W1l, us_W1r, us_b1, bufP2, N_PROD);
    agg_mean<<<aggP_grid, 256>>>(bufP1, offP, csrP, bufP0, N_PROD, E_PP);
    sage_gemm<128, true, true><<<148, 512, SMEM_DUAL>>>(bufP0, bufP1, it_W2l, it_W2r, it_b2, bufP3, N_PROD);
    sage_gemm<64, false, false><<<296, 512, SMEM_SINGLE>>>(bufP3, nullptr, it_Wlin, nullptr, it_blin, zprod, N_PROD);

    // UserGNN
    agg_mean<<<aggC_grid, 256>>>(x_prod, offC, csrC, bufC0, N_CUST, E_PC);
    sage_gemm<128, true, true><<<148, 512, SMEM_DUAL>>>(bufC0, x_cust, us_W2l, us_W2r, us_b2, bufC1, N_CUST);
    agg_mean<<<aggC_grid, 256>>>(bufP2, offC, csrC, bufC0, N_CUST, E_PC);
    sage_gemm<128, true, true><<<148, 512, SMEM_DUAL>>>(bufC0, bufC1, us_W3l, us_W3r, us_b3, bufC2, N_CUST);
    sage_gemm<64, false, false><<<296, 512, SMEM_SINGLE>>>(bufC2, nullptr, us_Wlin, nullptr, us_blin, zcust, N_CUST);

    // Edge decoder
    decoder_kernel<<<296, 512, SMEM_DEC>>>(zcust, zprod, eli, eli + E_LB,
                                           de_W1, de_b1, de_W2, de_b2,
                                           (float*)d_out, E_LB);
}

// round 4
// speedup vs baseline: 1.4288x; 1.3123x over previous
#include <cuda_runtime.h>
#include <cuda_bf16.h>
#include <cstdint>

#define N_PROD 100000
#define N_CUST 50000
#define HID    128
#define DOUT   64
#define E_PP   800000
#define E_PC   800000
#define E_LB   400000

typedef unsigned long long u64;

#define SWZ(x) ((x) ^ (((x) >> 3) & 0x70))

__device__ __forceinline__ uint32_t smem_u32(const void* p) {
    uint32_t a;
    asm("{ .reg .u64 t; cvta.to.shared.u64 t, %1; cvt.u32.u64 %0, t; }" : "=r"(a) : "l"(p));
    return a;
}

__device__ __forceinline__ void ldm4(uint32_t addr, uint32_t* r) {
    asm volatile("ldmatrix.sync.aligned.m8n8.x4.shared.b16 {%0,%1,%2,%3},[%4];"
                 : "=r"(r[0]), "=r"(r[1]), "=r"(r[2]), "=r"(r[3]) : "r"(addr));
}

__device__ __forceinline__ void mma16816(float* d, const uint32_t* a,
                                         uint32_t b0, uint32_t b1) {
    asm volatile(
        "mma.sync.aligned.m16n8k16.row.col.f32.bf16.bf16.f32 "
        "{%0,%1,%2,%3},{%4,%5,%6,%7},{%8,%9},{%0,%1,%2,%3};"
        : "+f"(d[0]), "+f"(d[1]), "+f"(d[2]), "+f"(d[3])
        : "r"(a[0]), "r"(a[1]), "r"(a[2]), "r"(a[3]), "r"(b0), "r"(b1));
}

// fp32 -> bf16 hi/lo split helpers
__device__ __forceinline__ void split1(float w, unsigned short& h, unsigned short& l) {
    __nv_bfloat16 hb = __float2bfloat16_rn(w);
    __nv_bfloat16 lb = __float2bfloat16_rn(w - __bfloat162float(hb));
    h = __bfloat16_as_ushort(hb);
    l = __bfloat16_as_ushort(lb);
}
__device__ __forceinline__ void split4(float4 v, u64& hp, u64& lp) {
    unsigned short h0, l0, h1, l1, h2, l2, h3, l3;
    split1(v.x, h0, l0); split1(v.y, h1, l1);
    split1(v.z, h2, l2); split1(v.w, h3, l3);
    hp = (u64)h0 | ((u64)h1 << 16) | ((u64)h2 << 32) | ((u64)h3 << 48);
    lp = (u64)l0 | ((u64)l1 << 16) | ((u64)l2 << 32) | ((u64)l3 << 48);
}

// f32x2 helpers for SIMT decoder
__device__ __forceinline__ u64 pack2(float lo, float hi) {
    u64 r; asm("mov.b64 %0,{%1,%2};" : "=l"(r) : "f"(lo), "f"(hi)); return r;
}
__device__ __forceinline__ u64 dup2(float a) {
    u64 r; asm("mov.b64 %0,{%1,%1};" : "=l"(r) : "f"(a)); return r;
}
__device__ __forceinline__ void fma2(u64& d, u64 a, u64 b) {
    asm("fma.rn.f32x2 %0,%1,%2,%0;" : "+l"(d) : "l"(a), "l"(b));
}
__device__ __forceinline__ void unpack2(u64 v, float& lo, float& hi) {
    asm("mov.b64 {%0,%1},%2;" : "=f"(lo), "=f"(hi) : "l"(v));
}

// ---------------------------------------------------------------------------
// Scratch
// ---------------------------------------------------------------------------
__device__ float g_bufP0[(size_t)N_PROD * HID];
__device__ float g_bufP1[(size_t)N_PROD * HID];
__device__ float g_bufP2[(size_t)N_PROD * HID];
__device__ float g_bufP3[(size_t)N_PROD * HID];
__device__ float g_bufC0[(size_t)N_CUST * HID];
__device__ float g_bufC1[(size_t)N_CUST * HID];
__device__ float g_bufC2[(size_t)N_CUST * HID];
__device__ float g_zprod[(size_t)N_PROD * DOUT];
__device__ float g_zcust[(size_t)N_CUST * DOUT];

__device__ int g_cnt[N_PROD];
__device__ int g_offP[N_PROD];
__device__ int g_curP[N_PROD];
__device__ int g_csrP[E_PP];
__device__ int g_offC[N_CUST];
__device__ int g_curC[N_CUST];
__device__ int g_csrC[E_PC];
__device__ int g_bsums[256];

// ---------------------------------------------------------------------------
// CSR build
// ---------------------------------------------------------------------------
__global__ void k_zero_int(int* p, int n) {
    int i = blockIdx.x * blockDim.x + threadIdx.x;
    if (i < n) p[i] = 0;
}
__global__ void k_count(const int* __restrict__ dst, int E, int* __restrict__ cnt) {
    int e = blockIdx.x * blockDim.x + threadIdx.x;
    if (e < E) atomicAdd(&cnt[dst[e]], 1);
}
__global__ void k_scan1(const int* __restrict__ cnt, int n, int* __restrict__ excl,
                        int* __restrict__ bsums) {
    __shared__ int s[1024];
    int gid = blockIdx.x * 1024 + threadIdx.x;
    int v = (gid < n) ? cnt[gid] : 0;
    s[threadIdx.x] = v;
    __syncthreads();
#pragma unroll
    for (int d = 1; d < 1024; d <<= 1) {
        int t = (threadIdx.x >= d) ? s[threadIdx.x - d] : 0;
        __syncthreads();
        s[threadIdx.x] += t;
        __syncthreads();
    }
    if (gid < n) excl[gid] = s[threadIdx.x] - v;
    if (threadIdx.x == 1023) bsums[blockIdx.x] = s[1023];
}
__global__ void k_scan2(int* bsums, int nb) {
    __shared__ int s[1024];
    int v = (threadIdx.x < nb) ? bsums[threadIdx.x] : 0;
    s[threadIdx.x] = v;
    __syncthreads();
#pragma unroll
    for (int d = 1; d < 1024; d <<= 1) {
        int t = (threadIdx.x >= d) ? s[threadIdx.x - d] : 0;
        __syncthreads();
        s[threadIdx.x] += t;
        __syncthreads();
    }
    if (threadIdx.x < nb) bsums[threadIdx.x] = s[threadIdx.x] - v;
}
__global__ void k_scan3(int* __restrict__ off, int* __restrict__ cur,
                        const int* __restrict__ bsums, int n) {
    int gid = blockIdx.x * 1024 + threadIdx.x;
    if (gid < n) {
        int v = off[gid] + bsums[blockIdx.x];
        off[gid] = v;
        cur[gid] = v;
    }
}
__global__ void k_fill(const int* __restrict__ src, const int* __restrict__ dst, int E,
                       int* __restrict__ cur, int* __restrict__ csr) {
    int e = blockIdx.x * blockDim.x + threadIdx.x;
    if (e < E) {
        int d = dst[e];
        int p = atomicAdd(&cur[d], 1);
        csr[p] = src[e];
    }
}

// ---------------------------------------------------------------------------
// Gather-side mean aggregation
// ---------------------------------------------------------------------------
__global__ void agg_mean(const float* __restrict__ x, const int* __restrict__ off,
                         const int* __restrict__ csr, float* __restrict__ outbuf,
                         int n, int E) {
    int w = (blockIdx.x * blockDim.x + threadIdx.x) >> 5;
    int lane = threadIdx.x & 31;
    if (w >= n) return;
    int beg = off[w];
    int end = (w + 1 < n) ? off[w + 1] : E;
    float4 acc = make_float4(0.f, 0.f, 0.f, 0.f);
    int j = beg;
    for (; j + 1 < end; j += 2) {
        int s0 = csr[j], s1 = csr[j + 1];
        float4 v0 = __ldg(reinterpret_cast<const float4*>(x + (size_t)s0 * HID + lane * 4));
        float4 v1 = __ldg(reinterpret_cast<const float4*>(x + (size_t)s1 * HID + lane * 4));
        acc.x += v0.x + v1.x; acc.y += v0.y + v1.y;
        acc.z += v0.z + v1.z; acc.w += v0.w + v1.w;
    }
    if (j < end) {
        int s0 = csr[j];
        float4 v0 = __ldg(reinterpret_cast<const float4*>(x + (size_t)s0 * HID + lane * 4));
        acc.x += v0.x; acc.y += v0.y; acc.z += v0.z; acc.w += v0.w;
    }
    float sc = (end > beg) ? 1.0f / (float)(end - beg) : 0.f;
    acc.x *= sc; acc.y *= sc; acc.z *= sc; acc.w *= sc;
    *reinterpret_cast<float4*>(outbuf + (size_t)w * HID + lane * 4) = acc;
}

// ---------------------------------------------------------------------------
// HMMA bf16x3 GEMM (mma.sync m16n8k16, persistent CTAs)
//   DUAL:  out = act([A|X] @ [Wl;Wr]^T + b)  K_TOT=256, N_OUT=128, MTILE=256
//   else:  out = A @ Wl^T + b                K_TOT=128, N_OUT=64,  MTILE=512
// 512 threads = 16 warps, each warp a 32x64 output tile.
// SMEM: [0..) bias | [1024..) A stage (hi|lo, SW128) | [BOFF..) W frags (hi|lo)
// ---------------------------------------------------------------------------
template <int N_OUT, int K_TOT, bool DUAL, bool RELU>
__global__ __launch_bounds__(512, 1) void hmma_gemm(
    const float* __restrict__ A, const float* __restrict__ X,
    const float* __restrict__ Wl, const float* __restrict__ Wr,
    const float* __restrict__ bias, float* __restrict__ out, int n)
{
    constexpr int KSTEPS = K_TOT / 16;
    constexpr int NFRT   = N_OUT / 8;
    constexpr int NF2    = NFRT / 2;
    constexpr int MTILE  = (N_OUT == 128) ? 256 : 512;
    constexpr int ASPLIT = MTILE * 128;                 // bytes per split
    constexpr int BOFF   = 1024 + 2 * ASPLIT;
    constexpr int BSPLIT = KSTEPS * NF2 * 32 * 16;      // bytes per split
    constexpr int NCHUNK = K_TOT / 64;

    extern __shared__ char smem[];
    const uint32_t sb = smem_u32(smem);
    const int tid = threadIdx.x;
    const int w = tid >> 5, lane = tid & 31;
    const int g     = (N_OUT == 128) ? (w & 1) : 0;        // n-group (64 cols)
    const int warpM = (N_OUT == 128) ? (w >> 1) * 32 : w * 32;

    float* bs = (float*)smem;
    if (tid < N_OUT) bs[tid] = bias[tid];

    // ---- W preload in fragment order (hi then lo), once per CTA ----
    // slot idx = ((s*KSTEPS+ks)*NF2 + nfp)*32 + lane ; 16B per slot (nf pair)
    for (int idx = tid; idx < 2 * KSTEPS * NF2 * 32; idx += 512) {
        int l = idx & 31;
        int rest = idx >> 5;
        int nfp = rest % NF2;
        int rest2 = rest / NF2;
        int ks = rest2 % KSTEPS;
        int s = rest2 / KSTEPS;
        uint32_t vals[4];
#pragma unroll
        for (int e = 0; e < 2; e++) {
            int nf = nfp * 2 + e;
            int nn = nf * 8 + (l >> 2);
            int k0 = ks * 16 + (l & 3) * 2;
            const float* wp = Wl;
            int kk = k0;
            if (DUAL && k0 >= 128) { wp = Wr; kk = k0 - 128; }
            float2 wa = *reinterpret_cast<const float2*>(wp + nn * 128 + kk);
            float2 wb = *reinterpret_cast<const float2*>(wp + nn * 128 + kk + 8);
            unsigned short h, lo;
            unsigned short r00, r01, r10, r11;
            split1(wa.x, h, lo); r00 = s ? lo : h;
            split1(wa.y, h, lo); r01 = s ? lo : h;
            split1(wb.x, h, lo); r10 = s ? lo : h;
            split1(wb.y, h, lo); r11 = s ? lo : h;
            vals[e * 2 + 0] = (uint32_t)r00 | ((uint32_t)r01 << 16);
            vals[e * 2 + 1] = (uint32_t)r10 | ((uint32_t)r11 << 16);
        }
        *reinterpret_cast<uint4*>(smem + BOFF + (size_t)idx * 16) =
            make_uint4(vals[0], vals[1], vals[2], vals[3]);
    }
    __syncthreads();

    const int ntiles = (n + MTILE - 1) / MTILE;

    for (int tt = blockIdx.x; tt < ntiles; tt += gridDim.x) {
        float acc[2][8][4];
#pragma unroll
        for (int t = 0; t < 2; t++)
#pragma unroll
            for (int nf = 0; nf < 8; nf++)
#pragma unroll
                for (int q = 0; q < 4; q++) acc[t][nf][q] = 0.f;

        for (int chunk = 0; chunk < NCHUNK; chunk++) {
            __syncthreads();
            // ---- stage A chunk: fp32 -> bf16 hi/lo, SW128-swizzled ----
            {
                const float* src = (DUAL && chunk >= 2) ? X : A;
                const int colbase = (chunk & 1) * 64;
                const int half = tid & 1;
                for (int r0 = tid >> 1; r0 < MTILE; r0 += 256) {
                    int gr = tt * MTILE + r0;
#pragma unroll
                    for (int j = 0; j < 8; j++) {
                        float4 v = make_float4(0.f, 0.f, 0.f, 0.f);
                        if (gr < n)
                            v = *reinterpret_cast<const float4*>(
                                src + (size_t)gr * 128 + colbase + half * 32 + j * 4);
                        u64 hp, lp; split4(v, hp, lp);
                        uint32_t sw = SWZ((uint32_t)(r0 * 128 + half * 64 + j * 8));
                        *(u64*)(smem + 1024 + sw) = hp;
                        *(u64*)(smem + 1024 + ASPLIT + sw) = lp;
                    }
                }
            }
            __syncthreads();

#pragma unroll
            for (int ksl = 0; ksl < 4; ksl++) {
                const int ks = chunk * 4 + ksl;
                // A fragments (hi and lo) for t=0,1 via ldmatrix.x4
                uint32_t ah[2][4], al[2][4];
#pragma unroll
                for (int t = 0; t < 2; t++) {
                    int arow = warpM + (lane & 15) + t * 16;
                    int colb = ksl * 32 + ((lane >> 4) << 4);
                    uint32_t off = SWZ((uint32_t)(arow * 128 + colb));
                    ldm4(sb + 1024 + off, ah[t]);
                    ldm4(sb + 1024 + ASPLIT + off, al[t]);
                }
                // B hi fragments: 4 x LDS.128 (nf pairs)
                uint4 Bq[4];
                {
                    size_t base = (size_t)BOFF +
                        ((size_t)(ks * NF2 + g * 4) * 32 + lane) * 16;
#pragma unroll
                    for (int p = 0; p < 4; p++)
                        Bq[p] = *reinterpret_cast<const uint4*>(smem + base + p * 512);
                }
#pragma unroll
                for (int t = 0; t < 2; t++)
#pragma unroll
                    for (int nf = 0; nf < 8; nf++) {
                        uint32_t b0 = (nf & 1) ? Bq[nf >> 1].z : Bq[nf >> 1].x;
                        uint32_t b1 = (nf & 1) ? Bq[nf >> 1].w : Bq[nf >> 1].y;
                        mma16816(acc[t][nf], ah[t], b0, b1);
                    }
#pragma unroll
                for (int t = 0; t < 2; t++)
#pragma unroll
                    for (int nf = 0; nf < 8; nf++) {
                        uint32_t b0 = (nf & 1) ? Bq[nf >> 1].z : Bq[nf >> 1].x;
                        uint32_t b1 = (nf & 1) ? Bq[nf >> 1].w : Bq[nf >> 1].y;
                        mma16816(acc[t][nf], al[t], b0, b1);
                    }
                // B lo fragments
                {
                    size_t base = (size_t)BOFF + BSPLIT +
                        ((size_t)(ks * NF2 + g * 4) * 32 + lane) * 16;
#pragma unroll
                    for (int p = 0; p < 4; p++)
                        Bq[p] = *reinterpret_cast<const uint4*>(smem + base + p * 512);
                }
#pragma unroll
                for (int t = 0; t < 2; t++)
#pragma unroll
                    for (int nf = 0; nf < 8; nf++) {
                        uint32_t b0 = (nf & 1) ? Bq[nf >> 1].z : Bq[nf >> 1].x;
                        uint32_t b1 = (nf & 1) ? Bq[nf >> 1].w : Bq[nf >> 1].y;
                        mma16816(acc[t][nf], ah[t], b0, b1);
                    }
            }
        }

        // ---- epilogue ----
#pragma unroll
        for (int t = 0; t < 2; t++) {
            int row0 = tt * MTILE + warpM + t * 16 + (lane >> 2);
#pragma unroll
            for (int nf = 0; nf < 8; nf++) {
                int col = g * 64 + nf * 8 + (lane & 3) * 2;
                if (row0 < n) {
                    float2 o;
                    o.x = acc[t][nf][0] + bs[col];
                    o.y = acc[t][nf][1] + bs[col + 1];
                    if (RELU) { o.x = fmaxf(o.x, 0.f); o.y = fmaxf(o.y, 0.f); }
                    *reinterpret_cast<float2*>(out + (size_t)row0 * N_OUT + col) = o;
                }
                if (row0 + 8 < n) {
                    float2 o;
                    o.x = acc[t][nf][2] + bs[col];
                    o.y = acc[t][nf][3] + bs[col + 1];
                    if (RELU) { o.x = fmaxf(o.x, 0.f); o.y = fmaxf(o.y, 0.f); }
                    *reinterpret_cast<float2*>(out + (size_t)(row0 + 8) * N_OUT + col) = o;
                }
            }
        }
    }
}

// ---------------------------------------------------------------------------
// SIMT decoder (round-2 version, f32x2 FMAs): 8 edges/warp
// ---------------------------------------------------------------------------
__launch_bounds__(512, 1)
__global__ void decoder_kernel(const float* __restrict__ zc, const float* __restrict__ zp,
                               const int* __restrict__ row, const int* __restrict__ col,
                               const float* __restrict__ W1, const float* __restrict__ b1,
                               const float* __restrict__ w2, const float* __restrict__ b2,
                               float* __restrict__ out, int nE) {
    constexpr int NOP = 68;
    constexpr int R = 8;
    extern __shared__ float smemf[];
    float* Ws = smemf;
    float* stage = smemf + 128 * NOP;

    int tid = threadIdx.x;
    for (int i = tid; i < 64 * 128; i += 512) {
        int o = i >> 7, k = i & 127;
        Ws[k * NOP + o] = W1[i];
    }
    __syncthreads();

    const int w = tid >> 5, lane = tid & 31;
    float* Zs = stage + w * (R * 128);

    float2 b1v = __ldg(reinterpret_cast<const float2*>(b1 + lane * 2));
    u64 bofs = pack2(b1v.x, b1v.y);
    float w20 = __ldg(w2 + lane * 2), w21 = __ldg(w2 + lane * 2 + 1);
    float b2v = __ldg(b2);

    for (int base = (blockIdx.x * 16 + w) * R; base < nE; base += gridDim.x * 16 * R) {
#pragma unroll
        for (int r = 0; r < R; r++) {
            int e = base + r;
            float4 v = make_float4(0.f, 0.f, 0.f, 0.f);
            if (e < nE) {
                if (lane < 16) {
                    int ri = __ldg(row + e);
                    v = *reinterpret_cast<const float4*>(zc + (size_t)ri * DOUT + lane * 4);
                } else {
                    int ci = __ldg(col + e);
                    v = *reinterpret_cast<const float4*>(zp + (size_t)ci * DOUT + (lane - 16) * 4);
                }
            }
            *reinterpret_cast<float4*>(Zs + r * 128 + lane * 4) = v;
        }
        __syncwarp();

        u64 acc[R];
#pragma unroll
        for (int r = 0; r < R; r++) acc[r] = bofs;

        for (int k0 = 0; k0 < 128; k0 += 4) {
            float4 z4[R];
#pragma unroll
            for (int r = 0; r < R; r++)
                z4[r] = *reinterpret_cast<const float4*>(Zs + r * 128 + k0);
#pragma unroll
            for (int kk = 0; kk < 4; kk++) {
                u64 wv = *reinterpret_cast<const u64*>(Ws + (k0 + kk) * NOP + lane * 2);
#pragma unroll
                for (int r = 0; r < R; r++) {
                    float z = (kk == 0) ? z4[r].x : (kk == 1) ? z4[r].y : (kk == 2) ? z4[r].z : z4[r].w;
                    u64 zd = dup2(z);
                    fma2(acc[r], zd, wv);
                }
            }
        }

#pragma unroll
        for (int r = 0; r < R; r++) {
            float h0, h1;
            unpack2(acc[r], h0, h1);
            h0 = fmaxf(h0, 0.f); h1 = fmaxf(h1, 0.f);
            float p = h0 * w20 + h1 * w21;
#pragma unroll
            for (int o = 16; o > 0; o >>= 1) p += __shfl_xor_sync(0xffffffff, p, o);
            if (lane == 0 && base + r < nE) out[base + r] = p + b2v;
        }
        __syncwarp();
    }
}

// ---------------------------------------------------------------------------
// Host orchestration
// ---------------------------------------------------------------------------
static void build_csr(const int* src, const int* dst, int E, int n,
                      int* cnt, int* off, int* cur, int* csr, int* bsums) {
    k_zero_int<<<(n + 255) / 256, 256>>>(cnt, n);
    k_count<<<(E + 255) / 256, 256>>>(dst, E, cnt);
    int nb = (n + 1023) / 1024;
    k_scan1<<<nb, 1024>>>(cnt, n, off, bsums);
    k_scan2<<<1, 1024>>>(bsums, nb);
    k_scan3<<<nb, 1024>>>(off, cur, bsums, n);
    k_fill<<<(E + 255) / 256, 256>>>(src, dst, E, cur, csr);
}

extern "C" void kernel_launch(void* const* d_in, const int* in_sizes, int n_in,
                              void* d_out, int out_size) {
    const float* x_prod = (const float*)d_in[0];
    const float* x_cust = (const float*)d_in[1];
    const int* pp = (const int*)d_in[2];
    const int* pc = (const int*)d_in[3];
    const int* eli = (const int*)d_in[4];

    bool sig = (in_sizes[6] == HID);
    const float* it_W1l = (const float*)d_in[5];
    const float* it_W1r = (const float*)d_in[sig ? 7 : 6];
    const float* it_b1  = (const float*)d_in[sig ? 6 : 7];
    const float* it_W2l = (const float*)d_in[8];
    const float* it_W2r = (const float*)d_in[sig ? 10 : 9];
    const float* it_b2  = (const float*)d_in[sig ? 9 : 10];
    const float* it_Wlin = (const float*)d_in[11];
    const float* it_blin = (const float*)d_in[12];
    const float* us_W1l = (const float*)d_in[13];
    const float* us_W1r = (const float*)d_in[sig ? 15 : 14];
    const float* us_b1  = (const float*)d_in[sig ? 14 : 15];
    const float* us_W2l = (const float*)d_in[16];
    const float* us_W2r = (const float*)d_in[sig ? 18 : 17];
    const float* us_b2  = (const float*)d_in[sig ? 17 : 18];
    const float* us_W3l = (const float*)d_in[19];
    const float* us_W3r = (const float*)d_in[sig ? 21 : 20];
    const float* us_b3  = (const float*)d_in[sig ? 20 : 21];
    const float* us_Wlin = (const float*)d_in[22];
    const float* us_blin = (const float*)d_in[23];
    const float* de_W1 = (const float*)d_in[24];
    const float* de_b1 = (const float*)d_in[25];
    const float* de_W2 = (const float*)d_in[26];
    const float* de_b2 = (const float*)d_in[27];

    float *bufP0, *bufP1, *bufP2, *bufP3, *bufC0, *bufC1, *bufC2, *zprod, *zcust;
    int *cnt, *offP, *curP, *csrP, *offC, *curC, *csrC, *bsums;
    cudaGetSymbolAddress((void**)&bufP0, g_bufP0);
    cudaGetSymbolAddress((void**)&bufP1, g_bufP1);
    cudaGetSymbolAddress((void**)&bufP2, g_bufP2);
    cudaGetSymbolAddress((void**)&bufP3, g_bufP3);
    cudaGetSymbolAddress((void**)&bufC0, g_bufC0);
    cudaGetSymbolAddress((void**)&bufC1, g_bufC1);
    cudaGetSymbolAddress((void**)&bufC2, g_bufC2);
    cudaGetSymbolAddress((void**)&zprod, g_zprod);
    cudaGetSymbolAddress((void**)&zcust, g_zcust);
    cudaGetSymbolAddress((void**)&cnt, g_cnt);
    cudaGetSymbolAddress((void**)&offP, g_offP);
    cudaGetSymbolAddress((void**)&curP, g_curP);
    cudaGetSymbolAddress((void**)&csrP, g_csrP);
    cudaGetSymbolAddress((void**)&offC, g_offC);
    cudaGetSymbolAddress((void**)&curC, g_curC);
    cudaGetSymbolAddress((void**)&csrC, g_csrC);
    cudaGetSymbolAddress((void**)&bsums, g_bsums);

    // SMEM: dual = 1024 + 2*256*128 + 2*16*8*32*16 = 197632
    //       single = 1024 + 2*512*128 + 2*8*4*32*16 = 164864
    constexpr int SM_DUAL = 1024 + 2 * 256 * 128 + 2 * 16 * 8 * 32 * 16;
    constexpr int SM_SNGL = 1024 + 2 * 512 * 128 + 2 * 8 * 4 * 32 * 16;
    constexpr int SM_DEC  = (128 * 68 + 16 * 8 * 128) * 4;
    cudaFuncSetAttribute(hmma_gemm<128, 256, true, true>,
                         cudaFuncAttributeMaxDynamicSharedMemorySize, SM_DUAL);
    cudaFuncSetAttribute(hmma_gemm<64, 128, false, false>,
                         cudaFuncAttributeMaxDynamicSharedMemorySize, SM_SNGL);
    cudaFuncSetAttribute(decoder_kernel,
                         cudaFuncAttributeMaxDynamicSharedMemorySize, SM_DEC);

    build_csr(pp, pp + E_PP, E_PP, N_PROD, cnt, offP, curP, csrP, bsums);
    build_csr(pc, pc + E_PC, E_PC, N_CUST, cnt, offC, curC, csrC, bsums);

    const int aggP_grid = (N_PROD * 32 + 255) / 256;
    const int aggC_grid = (N_CUST * 32 + 255) / 256;

    // ItemGNN + shared first product aggregation
    agg_mean<<<aggP_grid, 256>>>(x_prod, offP, csrP, bufP0, N_PROD, E_PP);
    hmma_gemm<128, 256, true, true><<<148, 512, SM_DUAL>>>(bufP0, x_prod, it_W1l, it_W1r, it_b1, bufP1, N_PROD);
    hmma_gemm<128, 256, true, true><<<148, 512, SM_DUAL>>>(bufP0, x_prod, us_W1l, us_W1r, us_b1, bufP2, N_PROD);
    agg_mean<<<aggP_grid, 256>>>(bufP1, offP, csrP, bufP0, N_PROD, E_PP);
    hmma_gemm<128, 256, true, true><<<148, 512, SM_DUAL>>>(bufP0, bufP1, it_W2l, it_W2r, it_b2, bufP3, N_PROD);
    hmma_gemm<64, 128, false, false><<<148, 512, SM_SNGL>>>(bufP3, nullptr, it_Wlin, nullptr, it_blin, zprod, N_PROD);

    // UserGNN
    agg_mean<<<aggC_grid, 256>>>(x_prod, offC, csrC, bufC0, N_CUST, E_PC);
    hmma_gemm<128, 256, true, true><<<148, 512, SM_DUAL>>>(bufC0, x_cust, us_W2l, us_W2r, us_b2, bufC1, N_CUST);
    agg_mean<<<aggC_grid, 256>>>(bufP2, offC, csrC, bufC0, N_CUST, E_PC);
    hmma_gemm<128, 256, true, true><<<148, 512, SM_DUAL>>>(bufC0, bufC1, us_W3l, us_W3r, us_b3, bufC2, N_CUST);
    hmma_gemm<64, 128, false, false><<<148, 512, SM_SNGL>>>(bufC2, nullptr, us_Wlin, nullptr, us_blin, zcust, N_CUST);

    // Edge decoder
    decoder_kernel<<<296, 512, SM_DEC>>>(zcust, zprod, eli, eli + E_LB,
                                         de_W1, de_b1, de_W2, de_b2,
                                         (float*)d_out, E_LB);
}